// round 15
// baseline (speedup 1.0000x reference)
#include <cuda_runtime.h>
#include <cuda_bf16.h>
#include <cstdint>

#define T_LEN 2048
#define NB 8
#define HD 512
#define VO 5000
#define VOP 5120                        // padded vocab rows
#define KE 1536                        // extended K: [hi | lo | hi] x [hi | hi | lo]
#define NT (T_LEN * NB)                 // 16384
#define Y_ELEMS (NB * T_LEN * VO)       // 81,920,000

typedef unsigned long long ull;

// ---------------- device scratch (static: no allocation allowed) ----------------
__device__ __align__(16) __nv_bfloat16 g_A[(size_t)NT * KE];    // 50.3 MB
__device__ __align__(16) __nv_bfloat16 g_B[(size_t)VOP * KE];   // 15.7 MB
__device__ unsigned g_cnt[128];         // per-16-step-chunk rnn completion counters (0..64)
__device__ unsigned g_done[128];        // per-bm gemm-epilogue counters (0..20)

// ---------------- helpers ----------------
__device__ __forceinline__ ull pack2(float x, float y) {
    ull r; asm("mov.b64 %0, {%1, %2};" : "=l"(r) : "f"(x), "f"(y)); return r;
}
__device__ __forceinline__ float2 unpack2(ull a) {
    float2 f; asm("mov.b64 {%0, %1}, %2;" : "=f"(f.x), "=f"(f.y) : "l"(a)); return f;
}
__device__ __forceinline__ void fma2(ull& d, ull a, ull b) {
    asm("fma.rn.f32x2 %0, %1, %2, %0;" : "+l"(d) : "l"(a), "l"(b));
}
__device__ __forceinline__ unsigned smem_u32(const void* p) {
    unsigned a;
    asm("{ .reg .u64 t; cvta.to.shared.u64 t, %1; cvt.u32.u64 %0, t; }" : "=r"(a) : "l"(p));
    return a;
}
__device__ __forceinline__ void st_async_f32(unsigned dst, unsigned mbar, float v) {
    asm volatile("st.async.shared::cluster.mbarrier::complete_tx::bytes.b32 [%0], %1, [%2];"
                 :: "r"(dst), "r"(__float_as_uint(v)), "r"(mbar) : "memory");
}
__device__ __forceinline__ unsigned mapa_u32(unsigned addr, unsigned rank) {
    unsigned ra;
    asm("mapa.shared::cluster.u32 %0, %1, %2;" : "=r"(ra) : "r"(addr), "r"(rank));
    return ra;
}
__device__ __forceinline__ void mbar_init(unsigned mb, unsigned cnt) {
    asm volatile("mbarrier.init.shared.b64 [%0], %1;" :: "r"(mb), "r"(cnt) : "memory");
}
__device__ __forceinline__ void mbar_arrive_expect(unsigned mb, unsigned bytes) {
    asm volatile("mbarrier.arrive.expect_tx.shared.b64 _, [%0], %1;"
                 :: "r"(mb), "r"(bytes) : "memory");
}
__device__ __forceinline__ void mbar_wait(unsigned mb, unsigned parity) {
    asm volatile(
        "{\n\t.reg .pred P;\n\tWL%=:\n\t"
        "mbarrier.try_wait.parity.acquire.cta.shared::cta.b64 P, [%0], %1, 0x989680;\n\t"
        "@!P bra WL%=;\n\t}"
        :: "r"(mb), "r"(parity) : "memory");
}

// ---------------- GEMM helpers (128x256 tile, occ-1 variant) ----------------
#define KCH 32
#define NCHUNK (KE / KCH)        // 48
#define ROWB 80                  // padded row bytes
#define ATILEB (128 * ROWB)      // 10240
#define BTILEB (256 * ROWB)      // 20480
#define STAGEB (ATILEB + BTILEB) // 30720
#define GSMEM_REQ 106496         // padded: forces 1 block/SM

#define RNN_BLOCKS 64
#define GEMM_BN 20               // VOP / 256
#define GEMM_BM 128              // NT / 128
#define FUSED_BLOCKS (RNN_BLOCKS + GEMM_BM * GEMM_BN)   // 2624

__device__ __forceinline__ void cpa16(uint32_t dst, const void* src) {
    asm volatile("cp.async.cg.shared.global [%0], [%1], 16;" :: "r"(dst), "l"(src));
}
__device__ __forceinline__ void ldm_x4(uint32_t* r, uint32_t addr) {
    asm volatile("ldmatrix.sync.aligned.m8n8.x4.shared.b16 {%0,%1,%2,%3}, [%4];"
                 : "=r"(r[0]), "=r"(r[1]), "=r"(r[2]), "=r"(r[3]) : "r"(addr));
}
__device__ __forceinline__ void mma_bf16(float* d, const uint32_t* a, const uint32_t* b) {
    asm volatile(
        "mma.sync.aligned.m16n8k16.row.col.f32.bf16.bf16.f32 "
        "{%0,%1,%2,%3}, {%4,%5,%6,%7}, {%8,%9}, {%0,%1,%2,%3};"
        : "+f"(d[0]), "+f"(d[1]), "+f"(d[2]), "+f"(d[3])
        : "r"(a[0]), "r"(a[1]), "r"(a[2]), "r"(a[3]), "r"(b[0]), "r"(b[1]));
}

// in-place softmax of one out row (256 threads)
__device__ __forceinline__ void softmax_row(float* p, int tid, float* red) {
    float v[20];
    float mx = -3.0e38f;
#pragma unroll
    for (int s = 0; s < 20; s++) {
        int i = tid + (s << 8);
        v[s] = (i < VO) ? p[i] : -3.0e38f;
        mx = fmaxf(mx, v[s]);
    }
#pragma unroll
    for (int o = 16; o; o >>= 1) mx = fmaxf(mx, __shfl_xor_sync(0xffffffffu, mx, o));
    if ((tid & 31) == 0) red[tid >> 5] = mx;
    __syncthreads();
    if (tid == 0) {
        float m = red[0];
#pragma unroll
        for (int w = 1; w < 8; w++) m = fmaxf(m, red[w]);
        red[0] = m;
    }
    __syncthreads();
    mx = red[0];

    float sum = 0.0f;
#pragma unroll
    for (int s = 0; s < 20; s++) {
        float e = __expf(v[s] - mx);
        v[s] = e;
        sum += e;
    }
#pragma unroll
    for (int o = 16; o; o >>= 1) sum += __shfl_xor_sync(0xffffffffu, sum, o);
    __syncthreads();
    if ((tid & 31) == 0) red[tid >> 5] = sum;
    __syncthreads();
    if (tid == 0) {
        float s2 = 0.0f;
#pragma unroll
        for (int w = 0; w < 8; w++) s2 += red[w];
        red[0] = s2;
    }
    __syncthreads();
    float rr = 1.0f / red[0];
#pragma unroll
    for (int s = 0; s < 20; s++) {
        int i = tid + (s << 8);
        if (i < VO) p[i] = v[s] * rr;
    }
    __syncthreads();
}

// ---------------- fused kernel: rnn (blocks 0-63) + gated GEMM + in-block softmax ----------------
__global__ __cluster_dims__(8, 1, 1) __launch_bounds__(256, 1)
void fused_kernel(const int* __restrict__ x, const float* __restrict__ E,
                  const float* __restrict__ Wh, const float* __restrict__ bh,
                  const float* __restrict__ bo, float* __restrict__ out) {
    extern __shared__ char dsm[];
    __shared__ __align__(16) float hbuf[2][HD];
    __shared__ __align__(8) ull bar[2];
    __shared__ int xs[T_LEN];
    __shared__ float red[8];

    const int bi  = blockIdx.x;
    const int tid = threadIdx.x;

    if (bi < RNN_BLOCKS) {
        // ======== RNN: exact round-7 structure (measured best); h_final -> out directly ========
        const int n   = bi >> 3;             // batch row
        const int r   = bi & 7;              // cluster rank
        const int f   = tid >> 2;            // 0..63
        const int sub = tid & 3;             // 0..3
        const int jg  = r * 64 + f;          // global feature

        ull w[64];
        {
            const float4* wr = (const float4*)(Wh + (size_t)jg * HD);
#pragma unroll
            for (int q = 0; q < 32; q++) {
                float4 v = __ldg(&wr[q * 4 + sub]);
                w[2 * q + 0] = pack2(v.x, v.y);
                w[2 * q + 1] = pack2(v.z, v.w);
            }
        }
        const float bias = (sub == 0) ? __ldg(&bh[jg]) : 0.0f;

        for (int i = tid; i < T_LEN; i += 256) xs[i] = x[n * T_LEN + i];
        if (tid < 128) ((float4*)hbuf[0])[tid] = make_float4(0.f, 0.f, 0.f, 0.f);

        const unsigned mb0 = smem_u32(&bar[0]);
        const unsigned mb1 = smem_u32(&bar[1]);
        if (tid == 0) {
            mbar_init(mb0, 1);
            mbar_init(mb1, 1);
            mbar_arrive_expect(mb0, 2048);
            mbar_arrive_expect(mb1, 2048);
        }
        __syncthreads();
        asm volatile("barrier.cluster.arrive.aligned;" ::: "memory");
        asm volatile("barrier.cluster.wait.aligned;"   ::: "memory");

        float eb = 0.0f;
        if (sub == 0) eb = __ldg(&E[(size_t)xs[0] * HD + jg]) + bias;

        const unsigned hb0 = smem_u32(&hbuf[0][jg]);
        const unsigned hb1 = smem_u32(&hbuf[1][jg]);

        for (int t = 0; t < T_LEN; t++) {
            const int par = t & 1;

            if (t >= 1) {
                mbar_wait(par ? mb1 : mb0, (unsigned)(((t - 1) >> 1) & 1));
                if (tid == 0) mbar_arrive_expect(par ? mb1 : mb0, 2048);
            }

            const ulonglong2* hp = (const ulonglong2*)hbuf[par];
            ull a0 = 0, a1 = 0, a2 = 0, a3 = 0;
#pragma unroll
            for (int q = 0; q < 32; q += 2) {
                ulonglong2 h0 = hp[q * 4 + sub];
                ulonglong2 h1 = hp[(q + 1) * 4 + sub];
                fma2(a0, w[2 * q + 0], h0.x);
                fma2(a1, w[2 * q + 1], h0.y);
                fma2(a2, w[2 * q + 2], h1.x);
                fma2(a3, w[2 * q + 3], h1.y);
            }
            float2 f0 = unpack2(a0), f1 = unpack2(a1), f2 = unpack2(a2), f3 = unpack2(a3);
            float s = (f0.x + f0.y) + (f1.x + f1.y) + (f2.x + f2.y) + (f3.x + f3.y);
            s += __shfl_down_sync(0xffffffffu, s, 2);
            s += __shfl_down_sync(0xffffffffu, s, 1);

            if (sub == 0) {
                float hv = tanhf(s + eb);
                __nv_bfloat16 hi = __float2bfloat16(hv);
                __nv_bfloat16 lo = __float2bfloat16(hv - __bfloat162float(hi));
                size_t base = (size_t)(t * 8 + n) * KE + jg;
                g_A[base]        = hi;
                g_A[base + 512]  = lo;
                g_A[base + 1024] = hi;
                if (t == T_LEN - 1) {
                    out[(size_t)Y_ELEMS + n * HD + jg] = hv;   // h_final folded in
                } else {
                    const unsigned dloc = (par ^ 1) ? hb1 : hb0;
                    const unsigned bloc = (par ^ 1) ? mb1 : mb0;
#pragma unroll
                    for (unsigned p = 0; p < 8; p++)
                        st_async_f32(mapa_u32(dloc, p), mapa_u32(bloc, p), hv);
                }
            }

            if (sub == 0 && t + 1 < T_LEN)
                eb = __ldg(&E[(size_t)xs[t + 1] * HD + jg]) + bias;

            if ((t & 15) == 15) {            // publish chunk t>>4
                __threadfence();
                __syncthreads();
                if (tid == 0) atomicAdd(&g_cnt[t >> 4], 1u);
            }
        }

        asm volatile("barrier.cluster.arrive.aligned;" ::: "memory");
        asm volatile("barrier.cluster.wait.aligned;"   ::: "memory");
    } else {
        // ======== GEMM (bm-major), gated on rnn progress; softmax after bm completes ========
        const int gi = bi - RNN_BLOCKS;
        const int bm = gi / GEMM_BN, bn = gi % GEMM_BN;
        const int lane = tid & 31, wid = tid >> 5;
        const int wm = wid >> 2, wn = wid & 3;       // 2 x 4 -> warp tile 64x64

        if (tid == 0) {
            while (*(volatile unsigned*)&g_cnt[bm] < 64u) __nanosleep(128);
        }
        __syncthreads();
        __threadfence();

        const uint32_t sb = smem_u32(dsm);
        const __nv_bfloat16* Ag = g_A + (size_t)bm * 128 * KE;
        const __nv_bfloat16* Bg = g_B + (size_t)bn * 256 * KE;

        auto load_stage = [&](int stage, int kc) {
            const uint32_t sA = sb + stage * STAGEB;
            const uint32_t sB = sA + ATILEB;
#pragma unroll
            for (int j = 0; j < 2; j++) {
                int tt = tid + j * 256;
                int row = tt >> 2, cc = tt & 3;
                cpa16(sA + row * ROWB + cc * 16, Ag + (size_t)row * KE + kc * KCH + cc * 8);
            }
#pragma unroll
            for (int j = 0; j < 4; j++) {
                int tt = tid + j * 256;
                int row = tt >> 2, cc = tt & 3;
                cpa16(sB + row * ROWB + cc * 16, Bg + (size_t)row * KE + kc * KCH + cc * 8);
            }
            asm volatile("cp.async.commit_group;");
        };

        float acc[4][8][4];
#pragma unroll
        for (int i = 0; i < 4; i++)
#pragma unroll
            for (int j = 0; j < 8; j++)
#pragma unroll
                for (int k = 0; k < 4; k++) acc[i][j][k] = 0.0f;

        load_stage(0, 0);
        load_stage(1, 1);

        const int a_row = (lane & 15);
        const int a_kb  = (lane >> 4) * 16;
        const int b_row = (lane & 7) + ((lane >> 4) * 8);
        const int b_kb  = ((lane >> 3) & 1) * 16;

        for (int cc = 0; cc < NCHUNK; cc++) {
            if (cc < NCHUNK - 1) asm volatile("cp.async.wait_group 1;");
            else                 asm volatile("cp.async.wait_group 0;");
            __syncthreads();
            if (cc + 2 < NCHUNK) load_stage((cc + 2) % 3, cc + 2);

            const uint32_t sA = sb + (cc % 3) * STAGEB;
            const uint32_t sB = sA + ATILEB;
#pragma unroll
            for (int ks = 0; ks < 2; ks++) {
                uint32_t a[4][4], b[4][4];
#pragma unroll
                for (int mf = 0; mf < 4; mf++)
                    ldm_x4(a[mf], sA + (wm * 64 + mf * 16 + a_row) * ROWB + ks * 32 + a_kb);
#pragma unroll
                for (int g = 0; g < 4; g++)
                    ldm_x4(b[g], sB + (wn * 64 + g * 16 + b_row) * ROWB + ks * 32 + b_kb);
#pragma unroll
                for (int mf = 0; mf < 4; mf++)
#pragma unroll
                    for (int nf = 0; nf < 8; nf++)
                        mma_bf16(acc[mf][nf], a[mf], &b[nf >> 1][(nf & 1) * 2]);
            }
        }

#pragma unroll
        for (int nf = 0; nf < 8; nf++) {
            const int col = bn * 256 + wn * 64 + nf * 8 + (lane & 3) * 2;
            if (col >= VO) continue;
            const float bx = __ldg(&bo[col]);
            const float by = __ldg(&bo[col + 1]);
#pragma unroll
            for (int mf = 0; mf < 4; mf++) {
                const int ml = wm * 64 + mf * 16 + (lane >> 2);
#pragma unroll
                for (int h = 0; h < 2; h++) {
                    const int m = bm * 128 + ml + h * 8;
                    const int orow = (m & 7) * T_LEN + (m >> 3);
                    float2 v = make_float2(acc[mf][nf][2 * h] + bx, acc[mf][nf][2 * h + 1] + by);
                    *(float2*)&out[(size_t)orow * VO + col] = v;
                }
            }
        }

        // ---- softmax for this bm: rendezvous (increment BEFORE waiting -> deadlock-free) ----
        __threadfence();
        __syncthreads();
        if (tid == 0) atomicAdd(&g_done[bm], 1u);
        if (tid == 0) {
            while (*(volatile unsigned*)&g_done[bm] < (unsigned)GEMM_BN) __nanosleep(128);
        }
        __syncthreads();
        __threadfence();

        // rows of this bm: local 0..127; this block handles 7 (bn<8) or 6 rows
        const int nrows = (bn < 8) ? 7 : 6;
        const int rstart = (bn < 8) ? bn * 7 : 56 + (bn - 8) * 6;
        for (int rr = 0; rr < nrows; rr++) {
            const int m = bm * 128 + rstart + rr;
            const int orow = (m & 7) * T_LEN + (m >> 3);
            softmax_row(out + (size_t)orow * VO, tid, red);
        }
    }
}

// ---------------- B' builder: Wo fp32 -> [hi, hi, lo] bf16; resets counters ----------------
__global__ __launch_bounds__(256) void convB_kernel(const float* __restrict__ Wo) {
    if (blockIdx.x == 0 && threadIdx.x < 128) {
        g_cnt[threadIdx.x] = 0;
        g_done[threadIdx.x] = 0;
    }
    int idx = blockIdx.x * 256 + threadIdx.x;
    if (idx >= VOP * HD) return;
    int row = idx >> 9, k = idx & 511;
    float v = (row < VO) ? __ldg(&Wo[row * HD + k]) : 0.0f;
    __nv_bfloat16 hi = __float2bfloat16(v);
    __nv_bfloat16 lo = __float2bfloat16(v - __bfloat162float(hi));
    size_t b = (size_t)row * KE;
    g_B[b + k]        = hi;
    g_B[b + 512 + k]  = hi;
    g_B[b + 1024 + k] = lo;
}

extern "C" void kernel_launch(void* const* d_in, const int* in_sizes, int n_in,
                              void* d_out, int out_size) {
    const int*   x  = (const int*)d_in[0];
    const float* E  = (const float*)d_in[1];
    const float* Wh = (const float*)d_in[2];
    const float* bh = (const float*)d_in[3];
    const float* Wo = (const float*)d_in[4];
    const float* bo = (const float*)d_in[5];
    float* out = (float*)d_out;

    cudaFuncSetAttribute(fused_kernel, cudaFuncAttributeMaxDynamicSharedMemorySize, GSMEM_REQ);

    convB_kernel<<<(VOP * HD + 255) / 256, 256>>>(Wo);
    fused_kernel<<<FUSED_BLOCKS, 256, GSMEM_REQ>>>(x, E, Wh, bh, bo, out);
}

// round 16
// speedup vs baseline: 1.1354x; 1.1354x over previous
#include <cuda_runtime.h>
#include <cuda_bf16.h>
#include <cstdint>

#define T_LEN 2048
#define NB 8
#define HD 512
#define VO 5000
#define VOP 5120                        // padded vocab rows
#define KE 1536                        // extended K: [hi | lo | hi] x [hi | hi | lo]
#define NT (T_LEN * NB)                 // 16384
#define Y_ELEMS (NB * T_LEN * VO)       // 81,920,000

typedef unsigned long long ull;

// ---------------- device scratch (static: no allocation allowed) ----------------
__device__ __align__(16) __nv_bfloat16 g_A[(size_t)NT * KE];    // 50.3 MB
__device__ __align__(16) __nv_bfloat16 g_B[(size_t)VOP * KE];   // 15.7 MB
__device__ unsigned g_cnt[128];         // per-16-step-chunk rnn completion counters (0..64)

// ---------------- helpers ----------------
__device__ __forceinline__ ull pack2(float x, float y) {
    ull r; asm("mov.b64 %0, {%1, %2};" : "=l"(r) : "f"(x), "f"(y)); return r;
}
__device__ __forceinline__ float2 unpack2(ull a) {
    float2 f; asm("mov.b64 {%0, %1}, %2;" : "=f"(f.x), "=f"(f.y) : "l"(a)); return f;
}
__device__ __forceinline__ void fma2(ull& d, ull a, ull b) {
    asm("fma.rn.f32x2 %0, %1, %2, %0;" : "+l"(d) : "l"(a), "l"(b));
}
__device__ __forceinline__ unsigned smem_u32(const void* p) {
    unsigned a;
    asm("{ .reg .u64 t; cvta.to.shared.u64 t, %1; cvt.u32.u64 %0, t; }" : "=r"(a) : "l"(p));
    return a;
}
__device__ __forceinline__ void st_async_f32(unsigned dst, unsigned mbar, float v) {
    asm volatile("st.async.shared::cluster.mbarrier::complete_tx::bytes.b32 [%0], %1, [%2];"
                 :: "r"(dst), "r"(__float_as_uint(v)), "r"(mbar) : "memory");
}
__device__ __forceinline__ unsigned mapa_u32(unsigned addr, unsigned rank) {
    unsigned ra;
    asm("mapa.shared::cluster.u32 %0, %1, %2;" : "=r"(ra) : "r"(addr), "r"(rank));
    return ra;
}
__device__ __forceinline__ void mbar_init(unsigned mb, unsigned cnt) {
    asm volatile("mbarrier.init.shared.b64 [%0], %1;" :: "r"(mb), "r"(cnt) : "memory");
}
__device__ __forceinline__ void mbar_arrive_expect(unsigned mb, unsigned bytes) {
    asm volatile("mbarrier.arrive.expect_tx.shared.b64 _, [%0], %1;"
                 :: "r"(mb), "r"(bytes) : "memory");
}
__device__ __forceinline__ void mbar_wait(unsigned mb, unsigned parity) {
    asm volatile(
        "{\n\t.reg .pred P;\n\tWL%=:\n\t"
        "mbarrier.try_wait.parity.acquire.cta.shared::cta.b64 P, [%0], %1, 0x989680;\n\t"
        "@!P bra WL%=;\n\t}"
        :: "r"(mb), "r"(parity) : "memory");
}

// ---------------- GEMM helpers (128x256 tile, occ-1 variant) ----------------
#define KCH 32
#define NCHUNK (KE / KCH)        // 48
#define ROWB 80                  // padded row bytes
#define ATILEB (128 * ROWB)      // 10240
#define BTILEB (256 * ROWB)      // 20480
#define STAGEB (ATILEB + BTILEB) // 30720
#define GSMEM_REQ 106496         // padded: forces 1 block/SM

#define RNN_BLOCKS 64
#define GEMM_BN 20               // VOP / 256
#define GEMM_BM 128              // NT / 128
#define FUSED_BLOCKS (RNN_BLOCKS + GEMM_BM * GEMM_BN)   // 2624

__device__ __forceinline__ void cpa16(uint32_t dst, const void* src) {
    asm volatile("cp.async.cg.shared.global [%0], [%1], 16;" :: "r"(dst), "l"(src));
}
__device__ __forceinline__ void ldm_x4(uint32_t* r, uint32_t addr) {
    asm volatile("ldmatrix.sync.aligned.m8n8.x4.shared.b16 {%0,%1,%2,%3}, [%4];"
                 : "=r"(r[0]), "=r"(r[1]), "=r"(r[2]), "=r"(r[3]) : "r"(addr));
}
__device__ __forceinline__ void mma_bf16(float* d, const uint32_t* a, const uint32_t* b) {
    asm volatile(
        "mma.sync.aligned.m16n8k16.row.col.f32.bf16.bf16.f32 "
        "{%0,%1,%2,%3}, {%4,%5,%6,%7}, {%8,%9}, {%0,%1,%2,%3};"
        : "+f"(d[0]), "+f"(d[1]), "+f"(d[2]), "+f"(d[3])
        : "r"(a[0]), "r"(a[1]), "r"(a[2]), "r"(a[3]), "r"(b[0]), "r"(b[1]));
}

// ---------------- fused kernel: rnn (blocks 0-63) + progress-gated GEMM ----------------
__global__ __cluster_dims__(8, 1, 1) __launch_bounds__(256, 1)
void fused_kernel(const int* __restrict__ x, const float* __restrict__ E,
                  const float* __restrict__ Wh, const float* __restrict__ bh,
                  const float* __restrict__ bo, float* __restrict__ out) {
    extern __shared__ char dsm[];
    __shared__ __align__(16) float hbuf[2][HD];
    __shared__ __align__(8) ull bar[2];
    __shared__ int xs[T_LEN];

    const int bi  = blockIdx.x;
    const int tid = threadIdx.x;

    if (bi < RNN_BLOCKS) {
        // ======== RNN: round-7 topology; hoisted mapa + push-first ordering ========
        const int n   = bi >> 3;             // batch row
        const int r   = bi & 7;              // cluster rank
        const int f   = tid >> 2;            // 0..63
        const int sub = tid & 3;             // 0..3
        const int jg  = r * 64 + f;          // global feature

        ull w[64];
        {
            const float4* wr = (const float4*)(Wh + (size_t)jg * HD);
#pragma unroll
            for (int q = 0; q < 32; q++) {
                float4 v = __ldg(&wr[q * 4 + sub]);
                w[2 * q + 0] = pack2(v.x, v.y);
                w[2 * q + 1] = pack2(v.z, v.w);
            }
        }
        const float bias = (sub == 0) ? __ldg(&bh[jg]) : 0.0f;

        for (int i = tid; i < T_LEN; i += 256) xs[i] = x[n * T_LEN + i];
        if (tid < 128) ((float4*)hbuf[0])[tid] = make_float4(0.f, 0.f, 0.f, 0.f);

        const unsigned mb0 = smem_u32(&bar[0]);
        const unsigned mb1 = smem_u32(&bar[1]);
        if (tid == 0) {
            mbar_init(mb0, 1);
            mbar_init(mb1, 1);
            mbar_arrive_expect(mb0, 2048);
            mbar_arrive_expect(mb1, 2048);
        }
        __syncthreads();
        asm volatile("barrier.cluster.arrive.aligned;" ::: "memory");
        asm volatile("barrier.cluster.wait.aligned;"   ::: "memory");

        float eb = 0.0f;
        if (sub == 0) eb = __ldg(&E[(size_t)xs[0] * HD + jg]) + bias;

        // hoisted remote addresses (same topology as round 7: sub0 pushes its feature to all 8)
        unsigned rdst0[8], rdst1[8], rmb[8];
        {
            const unsigned d0 = smem_u32(&hbuf[0][jg]);
            const unsigned d1 = smem_u32(&hbuf[1][jg]);
#pragma unroll
            for (int p = 0; p < 8; p++) {
                rdst0[p] = mapa_u32(d0, (unsigned)p);
                rdst1[p] = mapa_u32(d1, (unsigned)p);
                rmb[p]   = mapa_u32(mb0, (unsigned)p);   // remote mb1 = +8
            }
        }

        for (int t = 0; t < T_LEN; t++) {
            const int par = t & 1;

            if (t >= 1) {
                mbar_wait(par ? mb1 : mb0, (unsigned)(((t - 1) >> 1) & 1));
                if (tid == 0) mbar_arrive_expect(par ? mb1 : mb0, 2048);
            }

            const ulonglong2* hp = (const ulonglong2*)hbuf[par];
            ull a0 = 0, a1 = 0, a2 = 0, a3 = 0;
#pragma unroll
            for (int q = 0; q < 32; q += 2) {
                ulonglong2 h0 = hp[q * 4 + sub];
                ulonglong2 h1 = hp[(q + 1) * 4 + sub];
                fma2(a0, w[2 * q + 0], h0.x);
                fma2(a1, w[2 * q + 1], h0.y);
                fma2(a2, w[2 * q + 2], h1.x);
                fma2(a3, w[2 * q + 3], h1.y);
            }
            float2 f0 = unpack2(a0), f1 = unpack2(a1), f2 = unpack2(a2), f3 = unpack2(a3);
            float s = (f0.x + f0.y) + (f1.x + f1.y) + (f2.x + f2.y) + (f3.x + f3.y);
            s += __shfl_down_sync(0xffffffffu, s, 2);
            s += __shfl_down_sync(0xffffffffu, s, 1);

            if (sub == 0) {
                float hv = tanhf(s + eb);
                // ---- push FIRST (releases peers ASAP) ----
                if (t < T_LEN - 1) {
                    const unsigned mo = (par ^ 1) ? 8u : 0u;
#pragma unroll
                    for (int p = 0; p < 8; p++)
                        st_async_f32((par ^ 1) ? rdst1[p] : rdst0[p], rmb[p] + mo, hv);
                }
                // ---- then bookkeeping stores ----
                __nv_bfloat16 hi = __float2bfloat16(hv);
                __nv_bfloat16 lo = __float2bfloat16(hv - __bfloat162float(hi));
                size_t base = (size_t)(t * 8 + n) * KE + jg;
                g_A[base]        = hi;
                g_A[base + 512]  = lo;
                g_A[base + 1024] = hi;
                if (t == T_LEN - 1) out[(size_t)Y_ELEMS + n * HD + jg] = hv;  // h_final folded
            }

            if (sub == 0 && t + 1 < T_LEN)
                eb = __ldg(&E[(size_t)xs[t + 1] * HD + jg]) + bias;

            if ((t & 15) == 15) {            // publish chunk t>>4
                __threadfence();
                __syncthreads();
                if (tid == 0) atomicAdd(&g_cnt[t >> 4], 1u);
            }
        }

        asm volatile("barrier.cluster.arrive.aligned;" ::: "memory");
        asm volatile("barrier.cluster.wait.aligned;"   ::: "memory");
    } else {
        // ======== GEMM (bm-major), gated on rnn progress ========
        const int gi = bi - RNN_BLOCKS;
        const int bm = gi / GEMM_BN, bn = gi % GEMM_BN;
        const int lane = tid & 31, wid = tid >> 5;
        const int wm = wid >> 2, wn = wid & 3;       // 2 x 4 -> warp tile 64x64

        if (tid == 0) {
            while (*(volatile unsigned*)&g_cnt[bm] < 64u) __nanosleep(128);
        }
        __syncthreads();
        __threadfence();

        const uint32_t sb = smem_u32(dsm);
        const __nv_bfloat16* Ag = g_A + (size_t)bm * 128 * KE;
        const __nv_bfloat16* Bg = g_B + (size_t)bn * 256 * KE;

        auto load_stage = [&](int stage, int kc) {
            const uint32_t sA = sb + stage * STAGEB;
            const uint32_t sB = sA + ATILEB;
#pragma unroll
            for (int j = 0; j < 2; j++) {
                int tt = tid + j * 256;
                int row = tt >> 2, cc = tt & 3;
                cpa16(sA + row * ROWB + cc * 16, Ag + (size_t)row * KE + kc * KCH + cc * 8);
            }
#pragma unroll
            for (int j = 0; j < 4; j++) {
                int tt = tid + j * 256;
                int row = tt >> 2, cc = tt & 3;
                cpa16(sB + row * ROWB + cc * 16, Bg + (size_t)row * KE + kc * KCH + cc * 8);
            }
            asm volatile("cp.async.commit_group;");
        };

        float acc[4][8][4];
#pragma unroll
        for (int i = 0; i < 4; i++)
#pragma unroll
            for (int j = 0; j < 8; j++)
#pragma unroll
                for (int k = 0; k < 4; k++) acc[i][j][k] = 0.0f;

        load_stage(0, 0);
        load_stage(1, 1);

        const int a_row = (lane & 15);
        const int a_kb  = (lane >> 4) * 16;
        const int b_row = (lane & 7) + ((lane >> 4) * 8);
        const int b_kb  = ((lane >> 3) & 1) * 16;

        for (int cc = 0; cc < NCHUNK; cc++) {
            if (cc < NCHUNK - 1) asm volatile("cp.async.wait_group 1;");
            else                 asm volatile("cp.async.wait_group 0;");
            __syncthreads();
            if (cc + 2 < NCHUNK) load_stage((cc + 2) % 3, cc + 2);

            const uint32_t sA = sb + (cc % 3) * STAGEB;
            const uint32_t sB = sA + ATILEB;
#pragma unroll
            for (int ks = 0; ks < 2; ks++) {
                uint32_t a[4][4], b[4][4];
#pragma unroll
                for (int mf = 0; mf < 4; mf++)
                    ldm_x4(a[mf], sA + (wm * 64 + mf * 16 + a_row) * ROWB + ks * 32 + a_kb);
#pragma unroll
                for (int g = 0; g < 4; g++)
                    ldm_x4(b[g], sB + (wn * 64 + g * 16 + b_row) * ROWB + ks * 32 + b_kb);
#pragma unroll
                for (int mf = 0; mf < 4; mf++)
#pragma unroll
                    for (int nf = 0; nf < 8; nf++)
                        mma_bf16(acc[mf][nf], a[mf], &b[nf >> 1][(nf & 1) * 2]);
            }
        }

#pragma unroll
        for (int nf = 0; nf < 8; nf++) {
            const int col = bn * 256 + wn * 64 + nf * 8 + (lane & 3) * 2;
            if (col >= VO) continue;
            const float bx = __ldg(&bo[col]);
            const float by = __ldg(&bo[col + 1]);
#pragma unroll
            for (int mf = 0; mf < 4; mf++) {
                const int ml = wm * 64 + mf * 16 + (lane >> 2);
#pragma unroll
                for (int h = 0; h < 2; h++) {
                    const int m = bm * 128 + ml + h * 8;
                    const int orow = (m & 7) * T_LEN + (m >> 3);
                    float2 v = make_float2(acc[mf][nf][2 * h] + bx, acc[mf][nf][2 * h + 1] + by);
                    *(float2*)&out[(size_t)orow * VO + col] = v;
                }
            }
        }
    }
}

// ---------------- B' builder: Wo fp32 -> [hi, hi, lo] bf16; resets counters ----------------
__global__ __launch_bounds__(256) void convB_kernel(const float* __restrict__ Wo) {
    if (blockIdx.x == 0 && threadIdx.x < 128) g_cnt[threadIdx.x] = 0;
    int idx = blockIdx.x * 256 + threadIdx.x;
    if (idx >= VOP * HD) return;
    int row = idx >> 9, k = idx & 511;
    float v = (row < VO) ? __ldg(&Wo[row * HD + k]) : 0.0f;
    __nv_bfloat16 hi = __float2bfloat16(v);
    __nv_bfloat16 lo = __float2bfloat16(v - __bfloat162float(hi));
    size_t b = (size_t)row * KE;
    g_B[b + k]        = hi;
    g_B[b + 512 + k]  = hi;
    g_B[b + 1024 + k] = lo;
}

// ---------------- phase 3: in-place row softmax ----------------
__global__ __launch_bounds__(256) void softmax_kernel(float* __restrict__ out) {
    const int row = blockIdx.x;
    float* p = out + (size_t)row * VO;
    const int tid = threadIdx.x;
    __shared__ float red[8];

    float v[20];
    float mx = -3.0e38f;
#pragma unroll
    for (int s = 0; s < 20; s++) {
        int i = tid + (s << 8);
        v[s] = (i < VO) ? p[i] : -3.0e38f;
        mx = fmaxf(mx, v[s]);
    }
#pragma unroll
    for (int o = 16; o; o >>= 1) mx = fmaxf(mx, __shfl_xor_sync(0xffffffffu, mx, o));
    if ((tid & 31) == 0) red[tid >> 5] = mx;
    __syncthreads();
    if (tid == 0) {
        float m = red[0];
#pragma unroll
        for (int w = 1; w < 8; w++) m = fmaxf(m, red[w]);
        red[0] = m;
    }
    __syncthreads();
    mx = red[0];

    float sum = 0.0f;
#pragma unroll
    for (int s = 0; s < 20; s++) {
        float e = __expf(v[s] - mx);
        v[s] = e;
        sum += e;
    }
#pragma unroll
    for (int o = 16; o; o >>= 1) sum += __shfl_xor_sync(0xffffffffu, sum, o);
    __syncthreads();
    if ((tid & 31) == 0) red[tid >> 5] = sum;
    __syncthreads();
    if (tid == 0) {
        float s2 = 0.0f;
#pragma unroll
        for (int w = 0; w < 8; w++) s2 += red[w];
        red[0] = s2;
    }
    __syncthreads();
    float rr = 1.0f / red[0];
#pragma unroll
    for (int s = 0; s < 20; s++) {
        int i = tid + (s << 8);
        if (i < VO) p[i] = v[s] * rr;
    }
}

extern "C" void kernel_launch(void* const* d_in, const int* in_sizes, int n_in,
                              void* d_out, int out_size) {
    const int*   x  = (const int*)d_in[0];
    const float* E  = (const float*)d_in[1];
    const float* Wh = (const float*)d_in[2];
    const float* bh = (const float*)d_in[3];
    const float* Wo = (const float*)d_in[4];
    const float* bo = (const float*)d_in[5];
    float* out = (float*)d_out;

    cudaFuncSetAttribute(fused_kernel, cudaFuncAttributeMaxDynamicSharedMemorySize, GSMEM_REQ);

    convB_kernel<<<(VOP * HD + 255) / 256, 256>>>(Wo);
    fused_kernel<<<FUSED_BLOCKS, 256, GSMEM_REQ>>>(x, E, Wh, bh, bo, out);
    softmax_kernel<<<NT, 256>>>(out);
}